// round 13
// baseline (speedup 1.0000x reference)
#include <cuda_runtime.h>

#define N_NODES 100000
#define N_EDGES 3200000
#define D_FEAT  512

#define NBLK 1184            // 148 SMs x 8 blocks — guaranteed co-resident
#define T    256
#define DEG_RATIO 5          // bid%5==0 -> degree-atomic role in phase A
#define N_DEGB ((NBLK + DEG_RATIO - 1) / DEG_RATIO)   // 237
#define N_GEMB (NBLK - N_DEGB)                        // 947

// Scratch (device allocation forbidden). All zero at load; kernel restores
// zeros (g_deg in phase B, barrier counters at exit) so each call is identical.
__device__ float g_deg[N_NODES];
__device__ float g_h[N_NODES];      // h = x@W, overwritten with hn = h*dinv
__device__ float g_dinv[N_NODES];
__device__ unsigned g_bar[4];       // grid-barrier counters

// Software grid barrier. Safe because all NBLK blocks are co-resident
// (__launch_bounds__ caps regs at 32 => 8 blocks/SM fit on 148+ SMs).
__device__ __forceinline__ void grid_bar(int id) {
    __syncthreads();
    if (threadIdx.x == 0) {
        __threadfence();                       // publish this block's phase writes
        atomicAdd(&g_bar[id], 1u);
        while (atomicAdd(&g_bar[id], 0u) < NBLK) __nanosleep(64);
        __threadfence();                       // acquire other blocks' writes
    }
    __syncthreads();
}

__global__ void __launch_bounds__(T, 8) k_all(
    const int* __restrict__ src, const int* __restrict__ dst,
    const float* __restrict__ x, const float* __restrict__ W,
    float* __restrict__ out)
{
    const int bid = blockIdx.x, tid = threadIdx.x;

    // ---- Phase A: degree atomics (237 blocks) || h = x@W (947 blocks) ----
    if (bid % DEG_RATIO == 0) {
        int rank = bid / DEG_RATIO;                      // 0..236
        for (int e = rank * T + tid; e < N_EDGES / 4; e += N_DEGB * T) {
            int4 d = ((const int4*)dst)[e];
            atomicAdd(&g_deg[d.x], 1.0f);
            atomicAdd(&g_deg[d.y], 1.0f);
            atomicAdd(&g_deg[d.z], 1.0f);
            atomicAdd(&g_deg[d.w], 1.0f);
        }
    } else {
        __shared__ float sW[D_FEAT];
        for (int i = tid; i < D_FEAT; i += T) sW[i] = W[i];
        __syncthreads();

        int rank = bid - bid / DEG_RATIO - 1;            // 0..946
        int warp = tid >> 5, lane = tid & 31;
        const float4* wr = (const float4*)sW;
        for (int grp = rank; grp < N_NODES / 8; grp += N_GEMB) {
            int node = grp * 8 + warp;                   // warp per node
            const float4* xr = (const float4*)(x + (size_t)node * D_FEAT);
            float acc = 0.0f;
            #pragma unroll
            for (int i = 0; i < 4; i++) {
                int idx = lane + i * 32;                 // 128 float4 per row
                float4 v = xr[idx];
                float4 w = wr[idx];
                acc += v.x * w.x + v.y * w.y + v.z * w.z + v.w * w.w;
            }
            #pragma unroll
            for (int o = 16; o > 0; o >>= 1)
                acc += __shfl_xor_sync(0xffffffffu, acc, o);
            if (lane == 0) g_h[node] = acc;
        }
    }
    grid_bar(0);

    // ---- Phase B: dinv = rsqrt(deg+1); hn = h*dinv; out = self-loop term ----
    for (int i = bid * T + tid; i < N_NODES; i += NBLK * T) {
        float d = rsqrtf(g_deg[i] + 1.0f);               // +1 = self-loop
        g_deg[i]  = 0.0f;                                // restore invariant
        g_dinv[i] = d;
        float hn  = g_h[i] * d;
        g_h[i]  = hn;
        out[i]  = hn;                                    // self-loop (pre-dinv)
    }
    grid_bar(1);

    // ---- Phase C: out[dst] += hn[src]  (dinv[dst] factored out) ----
    for (int e = bid * T + tid; e < N_EDGES / 4; e += NBLK * T) {
        int4 s = ((const int4*)src)[e];
        int4 d = ((const int4*)dst)[e];
        atomicAdd(&out[d.x], g_h[s.x]);
        atomicAdd(&out[d.y], g_h[s.y]);
        atomicAdd(&out[d.z], g_h[s.z]);
        atomicAdd(&out[d.w], g_h[s.w]);
    }
    grid_bar(2);

    // ---- Phase D: out[i] = dinv[i] * (hn[i] + sum incoming) ----
    for (int i = bid * T + tid; i < N_NODES; i += NBLK * T)
        out[i] *= g_dinv[i];

    // Arrive-only completion; last block resets counters for the next replay.
    // Safe: counter3==NBLK implies every block exited all prior spin loops.
    __syncthreads();
    if (tid == 0) {
        __threadfence();
        unsigned t = atomicAdd(&g_bar[3], 1u);
        if (t + 1 == NBLK) {
            g_bar[0] = 0u; g_bar[1] = 0u; g_bar[2] = 0u; g_bar[3] = 0u;
        }
    }
}

extern "C" void kernel_launch(void* const* d_in, const int* in_sizes, int n_in,
                              void* d_out, int out_size) {
    const float* x    = (const float*)d_in[0];            // [N_NODES, D_FEAT]
    const int*   eidx = (const int*)d_in[1];              // [2, N_EDGES]
    const float* W    = (const float*)d_in[2];            // [D_FEAT, 1]
    float* out        = (float*)d_out;                    // [N_NODES]

    const int* src = eidx;                // row 0
    const int* dst = eidx + N_EDGES;      // row 1

    k_all<<<NBLK, T>>>(src, dst, x, W, out);
}

// round 16
// speedup vs baseline: 1.0289x; 1.0289x over previous
#include <cuda_runtime.h>

#define N_NODES 100000
#define N_EDGES 3200000
#define D_FEAT  512

#define NBLK 1184            // 148 SMs x 8 blocks — guaranteed co-resident
#define T    256
#define DEG_RATIO 5          // bid%5==0 -> degree-atomic role in phase A
#define N_DEGB ((NBLK + DEG_RATIO - 1) / DEG_RATIO)   // 237
#define N_GEMB (NBLK - N_DEGB)                        // 947

// Scratch (device allocation forbidden). All zero at load; kernel restores
// zeros (g_deg in phase B, barrier counters at exit) so each call is identical.
__device__ float g_deg[N_NODES];
__device__ float g_h[N_NODES];      // h = x@W, overwritten with hn = h*dinv
__device__ float g_dinv[N_NODES];
__device__ unsigned g_bar[4];       // grid-barrier counters

// Software grid barrier. Arrival is one atomicAdd per block; the SPIN is a
// volatile LOAD (not an RMW) — R13 showed 1184 leaders RMW-polling one L2
// address serializes the atomic ALU and stretched barriers by tens of us.
// L2 serves concurrent reads of one line at full read throughput.
__device__ __forceinline__ void grid_bar(int id) {
    __syncthreads();
    if (threadIdx.x == 0) {
        __threadfence();                       // publish this block's phase writes
        atomicAdd(&g_bar[id], 1u);
        unsigned ns = 32;
        while (*((volatile unsigned*)&g_bar[id]) < NBLK) {
            __nanosleep(ns);
            if (ns < 1024) ns <<= 1;           // backoff: fewer L2 polls
        }
        __threadfence();                       // acquire other blocks' writes
    }
    __syncthreads();
}

__global__ void __launch_bounds__(T, 8) k_all(
    const int* __restrict__ src, const int* __restrict__ dst,
    const float* __restrict__ x, const float* __restrict__ W,
    float* __restrict__ out)
{
    const int bid = blockIdx.x, tid = threadIdx.x;

    // ---- Phase A: degree atomics (237 blocks) || h = x@W (947 blocks) ----
    if (bid % DEG_RATIO == 0) {
        int rank = bid / DEG_RATIO;                      // 0..236
        for (int e = rank * T + tid; e < N_EDGES / 4; e += N_DEGB * T) {
            int4 d = ((const int4*)dst)[e];
            atomicAdd(&g_deg[d.x], 1.0f);
            atomicAdd(&g_deg[d.y], 1.0f);
            atomicAdd(&g_deg[d.z], 1.0f);
            atomicAdd(&g_deg[d.w], 1.0f);
        }
    } else {
        __shared__ float sW[D_FEAT];
        for (int i = tid; i < D_FEAT; i += T) sW[i] = W[i];
        __syncthreads();

        int rank = bid - bid / DEG_RATIO - 1;            // 0..946
        int warp = tid >> 5, lane = tid & 31;
        const float4* wr = (const float4*)sW;
        for (int grp = rank; grp < N_NODES / 8; grp += N_GEMB) {
            int node = grp * 8 + warp;                   // warp per node
            const float4* xr = (const float4*)(x + (size_t)node * D_FEAT);
            float acc = 0.0f;
            #pragma unroll
            for (int i = 0; i < 4; i++) {
                int idx = lane + i * 32;                 // 128 float4 per row
                float4 v = xr[idx];
                float4 w = wr[idx];
                acc += v.x * w.x + v.y * w.y + v.z * w.z + v.w * w.w;
            }
            #pragma unroll
            for (int o = 16; o > 0; o >>= 1)
                acc += __shfl_xor_sync(0xffffffffu, acc, o);
            if (lane == 0) g_h[node] = acc;
        }
    }
    grid_bar(0);

    // ---- Phase B: dinv = rsqrt(deg+1); hn = h*dinv; out = self-loop term ----
    for (int i = bid * T + tid; i < N_NODES; i += NBLK * T) {
        float d = rsqrtf(g_deg[i] + 1.0f);               // +1 = self-loop
        g_deg[i]  = 0.0f;                                // restore invariant
        g_dinv[i] = d;
        float hn  = g_h[i] * d;
        g_h[i]  = hn;
        out[i]  = hn;                                    // self-loop (pre-dinv)
    }
    grid_bar(1);

    // ---- Phase C: out[dst] += hn[src]  (dinv[dst] factored out) ----
    for (int e = bid * T + tid; e < N_EDGES / 4; e += NBLK * T) {
        int4 s = ((const int4*)src)[e];
        int4 d = ((const int4*)dst)[e];
        atomicAdd(&out[d.x], g_h[s.x]);
        atomicAdd(&out[d.y], g_h[s.y]);
        atomicAdd(&out[d.z], g_h[s.z]);
        atomicAdd(&out[d.w], g_h[s.w]);
    }
    grid_bar(2);

    // ---- Phase D: out[i] = dinv[i] * (hn[i] + sum incoming) ----
    for (int i = bid * T + tid; i < N_NODES; i += NBLK * T)
        out[i] *= g_dinv[i];

    // Arrive-only completion; last block resets counters for the next replay.
    // Safe: counter3==NBLK implies every block exited all prior spin loops.
    __syncthreads();
    if (tid == 0) {
        __threadfence();
        unsigned t = atomicAdd(&g_bar[3], 1u);
        if (t + 1 == NBLK) {
            g_bar[0] = 0u; g_bar[1] = 0u; g_bar[2] = 0u; g_bar[3] = 0u;
        }
    }
}

extern "C" void kernel_launch(void* const* d_in, const int* in_sizes, int n_in,
                              void* d_out, int out_size) {
    const float* x    = (const float*)d_in[0];            // [N_NODES, D_FEAT]
    const int*   eidx = (const int*)d_in[1];              // [2, N_EDGES]
    const float* W    = (const float*)d_in[2];            // [D_FEAT, 1]
    float* out        = (float*)d_out;                    // [N_NODES]

    const int* src = eidx;                // row 0
    const int* dst = eidx + N_EDGES;      // row 1

    k_all<<<NBLK, T>>>(src, dst, x, W, out);
}